// round 8
// baseline (speedup 1.0000x reference)
#include <cuda_runtime.h>
#include <math.h>

// Problem constants (fixed by the reference)
#define SEQL   2048
#define DMODEL 1024
#define DINNER 2048
#define DSTATE 16
#define DTRANK 64
#define DBCN   96          // DT_RANK + 2*D_STATE

// ---------------------------------------------------------------------------
// Scratch buffers: __device__ globals (allocation inside kernel_launch is
// forbidden; device globals are the sanctioned workaround).
// ---------------------------------------------------------------------------
__device__ float g_xz[2][(size_t)SEQL * 2 * DINNER];   // per-dir [t][4096]: u_pre | z
__device__ float g_u[2][(size_t)SEQL * DINNER];        // post conv+silu
__device__ float g_dbc[2][(size_t)SEQL * DBCN];        // dt | B | C
__device__ float g_delta[2][(size_t)SEQL * DINNER];    // softplus(dt@wdt.T + bdt)
__device__ float g_y[2][(size_t)SEQL * DINNER];        // scan output (fully fused)
__device__ float g_cat[(size_t)SEQL * 2 * DMODEL];     // [t][ fwd(1024) | bwd(1024) ]

// ---------------------------------------------------------------------------
// Generic register-tiled SGEMM:  C[M,N] = act( A[M,K] @ B[N,K]^T  (+ bias) )
//   - A row-major with leading dim lda; optional row flip on read (seq reverse)
//   - B is a weight matrix [N,K] row-major (ldb = K)
//   - C row-major ldc, optional row flip + column offset on write
//   - ACT: 0 none, 1 bias+softplus, 2 bias add
// M must be a multiple of BM and K a multiple of BK (true for all call sites);
// N is bounds-checked (needed for the N=96 skinny GEMM).
// ---------------------------------------------------------------------------
template<int BM, int BN, int BK, int TM, int TN, int ACT>
__global__ void __launch_bounds__((BM / TM) * (BN / TN))
gemm_atb(const float* __restrict__ A, const float* __restrict__ B,
         const float* __restrict__ bias, float* __restrict__ C,
         int M, int N, int K, int lda, int ldb, int ldc,
         int flipA, int flipC, int colOffC)
{
    constexpr int THREADS = (BM / TM) * (BN / TN);
    constexpr int TCOLS = BN / TN;
    __shared__ float As[BK][BM + 4];
    __shared__ float Bs[BK][BN + 4];

    const int tid = threadIdx.x;
    const int bm0 = blockIdx.y * BM;
    const int bn0 = blockIdx.x * BN;
    const int tr = tid / TCOLS;
    const int tc = tid % TCOLS;

    float acc[TM][TN];
#pragma unroll
    for (int i = 0; i < TM; i++)
#pragma unroll
        for (int j = 0; j < TN; j++) acc[i][j] = 0.f;

    for (int k0 = 0; k0 < K; k0 += BK) {
        // --- load A tile (BM x BK) as float4 along K ---
#pragma unroll 4
        for (int e = tid; e < BM * (BK / 4); e += THREADS) {
            int r  = e / (BK / 4);
            int k4 = e % (BK / 4);
            int gr = bm0 + r;
            int ar = flipA ? (M - 1 - gr) : gr;
            const float4 v =
                *reinterpret_cast<const float4*>(A + (size_t)ar * lda + k0 + k4 * 4);
            As[k4 * 4 + 0][r] = v.x;
            As[k4 * 4 + 1][r] = v.y;
            As[k4 * 4 + 2][r] = v.z;
            As[k4 * 4 + 3][r] = v.w;
        }
        // --- load B tile (BN x BK) as float4 along K, guard N ---
#pragma unroll 4
        for (int e = tid; e < BN * (BK / 4); e += THREADS) {
            int c  = e / (BK / 4);
            int k4 = e % (BK / 4);
            int gc = bn0 + c;
            float4 v = make_float4(0.f, 0.f, 0.f, 0.f);
            if (gc < N)
                v = *reinterpret_cast<const float4*>(B + (size_t)gc * ldb + k0 + k4 * 4);
            Bs[k4 * 4 + 0][c] = v.x;
            Bs[k4 * 4 + 1][c] = v.y;
            Bs[k4 * 4 + 2][c] = v.z;
            Bs[k4 * 4 + 3][c] = v.w;
        }
        __syncthreads();

#pragma unroll
        for (int kk = 0; kk < BK; kk++) {
            float ra[TM], rb[TN];
#pragma unroll
            for (int i = 0; i < TM; i++) ra[i] = As[kk][tr * TM + i];
#pragma unroll
            for (int j = 0; j < TN; j++) rb[j] = Bs[kk][tc * TN + j];
#pragma unroll
            for (int i = 0; i < TM; i++)
#pragma unroll
                for (int j = 0; j < TN; j++)
                    acc[i][j] = fmaf(ra[i], rb[j], acc[i][j]);
        }
        __syncthreads();
    }

    // --- epilogue ---
#pragma unroll
    for (int i = 0; i < TM; i++) {
        int gr = bm0 + tr * TM + i;
        int orow = flipC ? (M - 1 - gr) : gr;
#pragma unroll
        for (int j = 0; j < TN; j++) {
            int gc = bn0 + tc * TN + j;
            if (gc < N) {
                float v = acc[i][j];
                if (ACT == 1) {                       // bias + softplus
                    v += bias[gc];
                    v = (v > 20.f) ? v : log1pf(expf(v));
                } else if (ACT == 2) {                // bias
                    v += bias[gc];
                }
                C[(size_t)orow * ldc + colOffC + gc] = v;
            }
        }
    }
}

// ---------------------------------------------------------------------------
// Depthwise causal conv (D_CONV=4) + bias + silu.
// u[t][d] = silu( sum_k xz[t-3+k][d] * wconv[d][k] + bconv[d] )
// xz rows are [u_pre(2048) | z(2048)]; we read the first half.
// ---------------------------------------------------------------------------
__global__ void conv_silu_kernel(const float* __restrict__ xz,
                                 const float* __restrict__ wconv,
                                 const float* __restrict__ bconv,
                                 float* __restrict__ u)
{
    int idx = blockIdx.x * blockDim.x + threadIdx.x;
    if (idx >= SEQL * DINNER) return;
    int t = idx >> 11;          // / DINNER
    int d = idx & (DINNER - 1);
    const float* col = xz + d;  // column d, row stride 2*DINNER
    float w0 = wconv[d * 4 + 0], w1 = wconv[d * 4 + 1];
    float w2 = wconv[d * 4 + 2], w3 = wconv[d * 4 + 3];
    float s = bconv[d];
    if (t >= 3) s = fmaf(col[(size_t)(t - 3) * (2 * DINNER)], w0, s);
    if (t >= 2) s = fmaf(col[(size_t)(t - 2) * (2 * DINNER)], w1, s);
    if (t >= 1) s = fmaf(col[(size_t)(t - 1) * (2 * DINNER)], w2, s);
    s = fmaf(col[(size_t)t * (2 * DINNER)], w3, s);
    u[idx] = s / (1.f + __expf(-s));   // silu
}

// ---------------------------------------------------------------------------
// Selective scan. 2 channels per warp: lanes [0..15] -> channel 2w, lanes
// [16..31] -> channel 2w+1; lane&15 is the state index n. State h lives in a
// register. y = (sum_n h*C[n] + u*Dp) * silu(z), fused here.
// ---------------------------------------------------------------------------
__global__ void scan_kernel(const float* __restrict__ delta,
                            const float* __restrict__ u,
                            const float* __restrict__ dbc,
                            const float* __restrict__ xz,   // for z half
                            const float* __restrict__ Alog,
                            const float* __restrict__ Dp,
                            float* __restrict__ y)
{
    int warp = (blockIdx.x * blockDim.x + threadIdx.x) >> 5;
    int lane = threadIdx.x & 31;
    int n = lane & 15;
    int d = warp * 2 + (lane >> 4);

    float Adn = -expf(Alog[d * DSTATE + n]);   // A = -exp(Alog)
    float Dpd = Dp[d];
    float h = 0.f;

    for (int t = 0; t < SEQL; t++) {
        float dl = __ldg(&delta[(size_t)t * DINNER + d]);   // broadcast in half-warp
        float ut = __ldg(&u[(size_t)t * DINNER + d]);
        float Bn = __ldg(&dbc[t * DBCN + DTRANK + n]);
        float Cn = __ldg(&dbc[t * DBCN + DTRANK + DSTATE + n]);

        float dA = __expf(dl * Adn);            // dl>0, Adn<0 -> (0,1]
        h = fmaf(dA, h, dl * ut * Bn);
        float v = h * Cn;
        // reduce over 16 states (stays within each half-warp)
        v += __shfl_xor_sync(0xffffffffu, v, 8);
        v += __shfl_xor_sync(0xffffffffu, v, 4);
        v += __shfl_xor_sync(0xffffffffu, v, 2);
        v += __shfl_xor_sync(0xffffffffu, v, 1);
        if (n == 0) {
            float z = xz[(size_t)t * (2 * DINNER) + DINNER + d];
            float silu_z = z / (1.f + __expf(-z));
            y[(size_t)t * DINNER + d] = (v + ut * Dpd) * silu_z;
        }
    }
}

// ---------------------------------------------------------------------------
// kernel_launch: pure kernel launches on the default stream (graph-capturable).
// Input order per metadata: x, then f-block (win,wconv,bconv,wx,wdt,bdt,Alog,
// Dp,wout), then b-block, then wproj,bproj. Output: float32 [1,2048,1024].
// ---------------------------------------------------------------------------
extern "C" void kernel_launch(void* const* d_in, const int* in_sizes, int n_in,
                              void* d_out, int out_size)
{
    const float* x = (const float*)d_in[0];
    const float* win[2]   = {(const float*)d_in[1],  (const float*)d_in[10]};
    const float* wconv[2] = {(const float*)d_in[2],  (const float*)d_in[11]};
    const float* bconv[2] = {(const float*)d_in[3],  (const float*)d_in[12]};
    const float* wx[2]    = {(const float*)d_in[4],  (const float*)d_in[13]};
    const float* wdt[2]   = {(const float*)d_in[5],  (const float*)d_in[14]};
    const float* bdt[2]   = {(const float*)d_in[6],  (const float*)d_in[15]};
    const float* Alog[2]  = {(const float*)d_in[7],  (const float*)d_in[16]};
    const float* Dp[2]    = {(const float*)d_in[8],  (const float*)d_in[17]};
    const float* wout[2]  = {(const float*)d_in[9],  (const float*)d_in[18]};
    const float* wproj    = (const float*)d_in[19];
    const float* bproj    = (const float*)d_in[20];

    float *xz, *u, *dbc, *delta, *y, *cat;
    cudaGetSymbolAddress((void**)&xz,    g_xz);
    cudaGetSymbolAddress((void**)&u,     g_u);
    cudaGetSymbolAddress((void**)&dbc,   g_dbc);
    cudaGetSymbolAddress((void**)&delta, g_delta);
    cudaGetSymbolAddress((void**)&y,     g_y);
    cudaGetSymbolAddress((void**)&cat,   g_cat);

    const size_t XZS = (size_t)SEQL * 2 * DINNER;
    const size_t US  = (size_t)SEQL * DINNER;
    const size_t DBS = (size_t)SEQL * DBCN;

    for (int dir = 0; dir < 2; dir++) {
        float* xzd  = xz    + dir * XZS;
        float* ud   = u     + dir * US;
        float* dbcd = dbc   + dir * DBS;
        float* deld = delta + dir * US;
        float* yd   = y     + dir * US;

        // 1) xz = x(dir-flipped) @ win^T   [2048 x 4096], K=1024
        gemm_atb<128, 128, 16, 8, 8, 0>
            <<<dim3(2 * DINNER / 128, SEQL / 128), 256>>>(
                x, win[dir], nullptr, xzd,
                SEQL, 2 * DINNER, DMODEL,
                DMODEL, DMODEL, 2 * DINNER, /*flipA=*/dir, 0, 0);

        // 2) depthwise conv + silu -> u
        conv_silu_kernel<<<(SEQL * DINNER) / 256, 256>>>(
            xzd, wconv[dir], bconv[dir], ud);

        // 3) dbc = u @ wx^T   [2048 x 96], K=2048  (skinny tile: 32x96)
        gemm_atb<32, 96, 16, 2, 6, 0>
            <<<dim3(1, SEQL / 32), 256>>>(
                ud, wx[dir], nullptr, dbcd,
                SEQL, DBCN, DINNER,
                DINNER, DINNER, DBCN, 0, 0, 0);

        // 4) delta = softplus(dt @ wdt^T + bdt)   [2048 x 2048], K=64
        //    (A = dbc with lda=96, columns 0..63 are dt)
        gemm_atb<128, 128, 16, 8, 8, 1>
            <<<dim3(DINNER / 128, SEQL / 128), 256>>>(
                dbcd, wdt[dir], bdt[dir], deld,
                SEQL, DINNER, DTRANK,
                DBCN, DTRANK, DINNER, 0, 0, 0);

        // 5) selective scan (fused +u*Dp and *silu(z)) -> y
        scan_kernel<<<(DINNER / 2) / 8, 256>>>(
            deld, ud, dbcd, xzd, Alog[dir], Dp[dir], yd);

        // 6) dir output = y @ wout^T -> cat[:, dir*1024 : ...], rows un-flipped for b
        gemm_atb<128, 128, 16, 8, 8, 0>
            <<<dim3(DMODEL / 128, SEQL / 128), 256>>>(
                yd, wout[dir], nullptr, cat,
                SEQL, DMODEL, DINNER,
                DINNER, DINNER, 2 * DMODEL, 0, /*flipC=*/dir, /*colOff=*/dir * DMODEL);
    }

    // 7) out = cat @ wproj^T + bproj   [2048 x 1024], K=2048
    gemm_atb<128, 128, 16, 8, 8, 2>
        <<<dim3(DMODEL / 128, SEQL / 128), 256>>>(
            cat, wproj, bproj, (float*)d_out,
            SEQL, DMODEL, 2 * DMODEL,
            2 * DMODEL, 2 * DMODEL, DMODEL, 0, 0, 0);
}

// round 9
// speedup vs baseline: 1.0169x; 1.0169x over previous
#include <cuda_runtime.h>
#include <math.h>

// Problem constants (fixed by the reference)
#define SEQL   2048
#define DMODEL 1024
#define DINNER 2048
#define DSTATE 16
#define DTRANK 64
#define DBCN   96          // DT_RANK + 2*D_STATE

// ---------------------------------------------------------------------------
// Scratch buffers: __device__ globals.
// ---------------------------------------------------------------------------
__device__ float g_xz[2][(size_t)SEQL * 2 * DINNER];   // per-dir [t][4096]: u_pre | z
__device__ float g_u[2][(size_t)SEQL * DINNER];        // post conv+silu
__device__ float g_dbc[2][(size_t)SEQL * DBCN];        // dt | B | C
__device__ float g_delta[2][(size_t)SEQL * DINNER];    // softplus(dt@wdt.T + bdt)
__device__ float g_y[2][(size_t)SEQL * DINNER];        // scan output (fully fused)
__device__ float g_cat[(size_t)SEQL * 2 * DMODEL];     // [t][ fwd(1024) | bwd(1024) ]

// ---------------------------------------------------------------------------
// Packed f32x2 helpers (sm_103a packed fp32 path — 2 FMAs per instruction)
// ---------------------------------------------------------------------------
__device__ __forceinline__ unsigned long long pack2(float lo, float hi) {
    unsigned long long r;
    asm("mov.b64 %0, {%1, %2};" : "=l"(r) : "f"(lo), "f"(hi));
    return r;
}
__device__ __forceinline__ void fma_f32x2(unsigned long long& d,
                                          unsigned long long a,
                                          unsigned long long b) {
    asm("fma.rn.f32x2 %0, %1, %2, %0;" : "+l"(d) : "l"(a), "l"(b));
}
__device__ __forceinline__ float2 unpack2(unsigned long long v) {
    float2 r;
    asm("mov.b64 {%0, %1}, %2;" : "=f"(r.x), "=f"(r.y) : "l"(v));
    return r;
}

// ---------------------------------------------------------------------------
// Big-tile SGEMM, f32x2 packed, double-buffered smem with register staging.
//   C[M,N] = act( A[M,K] @ B[N,K]^T (+ bias) )
// Fixed tile: BM=BN=128, BK=16, TM=TN=8, 256 threads.
// Requirements (hold at all call sites): M%128==0, N%128==0, K%16==0,
// lda/ldb/ldc multiples of 4, pointers 16B-aligned.
// ACT: 0 none, 1 bias+softplus, 2 bias add.
// ---------------------------------------------------------------------------
template<int ACT>
__global__ void __launch_bounds__(256)
gemm128(const float* __restrict__ A, const float* __restrict__ B,
        const float* __restrict__ bias, float* __restrict__ C,
        int M, int N, int K, int lda, int ldb, int ldc,
        int flipA, int flipC, int colOffC)
{
    constexpr int BM = 128, BN = 128, BK = 16, TM = 8, TN = 8;
    constexpr int THREADS = 256;
    __shared__ float As[2][BK][BM + 4];
    __shared__ float Bs[2][BK][BN + 4];

    const int tid = threadIdx.x;
    const int bm0 = blockIdx.y * BM;
    const int bn0 = blockIdx.x * BN;
    const int tr = tid / 16;       // 16x16 thread grid
    const int tc = tid % 16;

    unsigned long long acc[TM][TN / 2];
#pragma unroll
    for (int i = 0; i < TM; i++)
#pragma unroll
        for (int j = 0; j < TN / 2; j++) acc[i][j] = 0ull;

    // Each thread stages 2 float4 of A and 2 float4 of B per tile.
    // Element e in [0, BM*BK/4): row r = e/(BK/4), quad k4 = e%(BK/4).
    float4 stA[2], stB[2];
    const int r0 = tid / (BK / 4);               // rows this thread loads
    const int r1 = (tid + THREADS) / (BK / 4);
    const int k40 = tid % (BK / 4);
    const int k41 = (tid + THREADS) % (BK / 4);

    const int nIter = K / BK;

    auto LOAD = [&](int k0) {
        int ar0 = flipA ? (M - 1 - (bm0 + r0)) : (bm0 + r0);
        int ar1 = flipA ? (M - 1 - (bm0 + r1)) : (bm0 + r1);
        stA[0] = *reinterpret_cast<const float4*>(A + (size_t)ar0 * lda + k0 + k40 * 4);
        stA[1] = *reinterpret_cast<const float4*>(A + (size_t)ar1 * lda + k0 + k41 * 4);
        stB[0] = *reinterpret_cast<const float4*>(B + (size_t)(bn0 + r0) * ldb + k0 + k40 * 4);
        stB[1] = *reinterpret_cast<const float4*>(B + (size_t)(bn0 + r1) * ldb + k0 + k41 * 4);
    };
    auto STORE = [&](int buf) {
        As[buf][k40 * 4 + 0][r0] = stA[0].x;
        As[buf][k40 * 4 + 1][r0] = stA[0].y;
        As[buf][k40 * 4 + 2][r0] = stA[0].z;
        As[buf][k40 * 4 + 3][r0] = stA[0].w;
        As[buf][k41 * 4 + 0][r1] = stA[1].x;
        As[buf][k41 * 4 + 1][r1] = stA[1].y;
        As[buf][k41 * 4 + 2][r1] = stA[1].z;
        As[buf][k41 * 4 + 3][r1] = stA[1].w;
        Bs[buf][k40 * 4 + 0][r0] = stB[0].x;
        Bs[buf][k40 * 4 + 1][r0] = stB[0].y;
        Bs[buf][k40 * 4 + 2][r0] = stB[0].z;
        Bs[buf][k40 * 4 + 3][r0] = stB[0].w;
        Bs[buf][k41 * 4 + 0][r1] = stB[1].x;
        Bs[buf][k41 * 4 + 1][r1] = stB[1].y;
        Bs[buf][k41 * 4 + 2][r1] = stB[1].z;
        Bs[buf][k41 * 4 + 3][r1] = stB[1].w;
    };

    LOAD(0);
    STORE(0);
    __syncthreads();

    int buf = 0;
    for (int it = 0; it < nIter; it++) {
        if (it + 1 < nIter) LOAD((it + 1) * BK);   // LDGs in flight during compute

#pragma unroll
        for (int kk = 0; kk < BK; kk++) {
            const float4 a0 = *reinterpret_cast<const float4*>(&As[buf][kk][tr * TM]);
            const float4 a1 = *reinterpret_cast<const float4*>(&As[buf][kk][tr * TM + 4]);
            const float4 b0 = *reinterpret_cast<const float4*>(&Bs[buf][kk][tc * TN]);
            const float4 b1 = *reinterpret_cast<const float4*>(&Bs[buf][kk][tc * TN + 4]);
            unsigned long long bv[4] = {pack2(b0.x, b0.y), pack2(b0.z, b0.w),
                                        pack2(b1.x, b1.y), pack2(b1.z, b1.w)};
            float av[8] = {a0.x, a0.y, a0.z, a0.w, a1.x, a1.y, a1.z, a1.w};
#pragma unroll
            for (int i = 0; i < TM; i++) {
                unsigned long long ai = pack2(av[i], av[i]);
#pragma unroll
                for (int j = 0; j < TN / 2; j++) fma_f32x2(acc[i][j], ai, bv[j]);
            }
        }

        if (it + 1 < nIter) {
            STORE(buf ^ 1);
            __syncthreads();
        }
        buf ^= 1;
    }

    // --- epilogue (vectorized STG.128) ---
#pragma unroll
    for (int i = 0; i < TM; i++) {
        int gr = bm0 + tr * TM + i;
        int orow = flipC ? (M - 1 - gr) : gr;
        float2 p0 = unpack2(acc[i][0]);
        float2 p1 = unpack2(acc[i][1]);
        float2 p2 = unpack2(acc[i][2]);
        float2 p3 = unpack2(acc[i][3]);
        float v[8] = {p0.x, p0.y, p1.x, p1.y, p2.x, p2.y, p3.x, p3.y};
        if (ACT != 0) {
#pragma unroll
            for (int j = 0; j < 8; j++) {
                int gc = bn0 + tc * TN + j;
                v[j] += bias[gc];
                if (ACT == 1) v[j] = (v[j] > 20.f) ? v[j] : log1pf(expf(v[j]));
            }
        }
        float* dst = C + (size_t)orow * ldc + colOffC + bn0 + tc * TN;
        *reinterpret_cast<float4*>(dst)     = make_float4(v[0], v[1], v[2], v[3]);
        *reinterpret_cast<float4*>(dst + 4) = make_float4(v[4], v[5], v[6], v[7]);
    }
}

// ---------------------------------------------------------------------------
// Scalar tiled SGEMM kept for the skinny N=96 case (bounds-checked on N).
// ---------------------------------------------------------------------------
template<int BM, int BN, int BK, int TM, int TN>
__global__ void __launch_bounds__((BM / TM) * (BN / TN))
gemm_atb(const float* __restrict__ A, const float* __restrict__ B,
         float* __restrict__ C,
         int M, int N, int K, int lda, int ldb, int ldc)
{
    constexpr int THREADS = (BM / TM) * (BN / TN);
    constexpr int TCOLS = BN / TN;
    __shared__ float As[BK][BM + 4];
    __shared__ float Bs[BK][BN + 4];

    const int tid = threadIdx.x;
    const int bm0 = blockIdx.y * BM;
    const int bn0 = blockIdx.x * BN;
    const int tr = tid / TCOLS;
    const int tc = tid % TCOLS;

    float acc[TM][TN];
#pragma unroll
    for (int i = 0; i < TM; i++)
#pragma unroll
        for (int j = 0; j < TN; j++) acc[i][j] = 0.f;

    for (int k0 = 0; k0 < K; k0 += BK) {
        for (int e = tid; e < BM * (BK / 4); e += THREADS) {
            int r = e / (BK / 4), k4 = e % (BK / 4);
            const float4 v = *reinterpret_cast<const float4*>(
                A + (size_t)(bm0 + r) * lda + k0 + k4 * 4);
            As[k4 * 4 + 0][r] = v.x; As[k4 * 4 + 1][r] = v.y;
            As[k4 * 4 + 2][r] = v.z; As[k4 * 4 + 3][r] = v.w;
        }
        for (int e = tid; e < BN * (BK / 4); e += THREADS) {
            int c = e / (BK / 4), k4 = e % (BK / 4);
            int gc = bn0 + c;
            float4 v = make_float4(0.f, 0.f, 0.f, 0.f);
            if (gc < N)
                v = *reinterpret_cast<const float4*>(B + (size_t)gc * ldb + k0 + k4 * 4);
            Bs[k4 * 4 + 0][c] = v.x; Bs[k4 * 4 + 1][c] = v.y;
            Bs[k4 * 4 + 2][c] = v.z; Bs[k4 * 4 + 3][c] = v.w;
        }
        __syncthreads();
#pragma unroll
        for (int kk = 0; kk < BK; kk++) {
            float ra[TM], rb[TN];
#pragma unroll
            for (int i = 0; i < TM; i++) ra[i] = As[kk][tr * TM + i];
#pragma unroll
            for (int j = 0; j < TN; j++) rb[j] = Bs[kk][tc * TN + j];
#pragma unroll
            for (int i = 0; i < TM; i++)
#pragma unroll
                for (int j = 0; j < TN; j++)
                    acc[i][j] = fmaf(ra[i], rb[j], acc[i][j]);
        }
        __syncthreads();
    }
#pragma unroll
    for (int i = 0; i < TM; i++) {
        int gr = bm0 + tr * TM + i;
#pragma unroll
        for (int j = 0; j < TN; j++) {
            int gc = bn0 + tc * TN + j;
            if (gc < N) C[(size_t)gr * ldc + gc] = acc[i][j];
        }
    }
}

// ---------------------------------------------------------------------------
// Depthwise causal conv (D_CONV=4) + bias + silu.
// ---------------------------------------------------------------------------
__global__ void conv_silu_kernel(const float* __restrict__ xz,
                                 const float* __restrict__ wconv,
                                 const float* __restrict__ bconv,
                                 float* __restrict__ u)
{
    int idx = blockIdx.x * blockDim.x + threadIdx.x;
    if (idx >= SEQL * DINNER) return;
    int t = idx >> 11;
    int d = idx & (DINNER - 1);
    const float* col = xz + d;
    float w0 = wconv[d * 4 + 0], w1 = wconv[d * 4 + 1];
    float w2 = wconv[d * 4 + 2], w3 = wconv[d * 4 + 3];
    float s = bconv[d];
    if (t >= 3) s = fmaf(col[(size_t)(t - 3) * (2 * DINNER)], w0, s);
    if (t >= 2) s = fmaf(col[(size_t)(t - 2) * (2 * DINNER)], w1, s);
    if (t >= 1) s = fmaf(col[(size_t)(t - 1) * (2 * DINNER)], w2, s);
    s = fmaf(col[(size_t)t * (2 * DINNER)], w3, s);
    u[idx] = s / (1.f + __expf(-s));
}

// ---------------------------------------------------------------------------
// Selective scan (2 channels/warp, states in registers, fused epilogue).
// ---------------------------------------------------------------------------
__global__ void scan_kernel(const float* __restrict__ delta,
                            const float* __restrict__ u,
                            const float* __restrict__ dbc,
                            const float* __restrict__ xz,
                            const float* __restrict__ Alog,
                            const float* __restrict__ Dp,
                            float* __restrict__ y)
{
    int warp = (blockIdx.x * blockDim.x + threadIdx.x) >> 5;
    int lane = threadIdx.x & 31;
    int n = lane & 15;
    int d = warp * 2 + (lane >> 4);

    float Adn = -expf(Alog[d * DSTATE + n]);
    float Dpd = Dp[d];
    float h = 0.f;

    for (int t = 0; t < SEQL; t++) {
        float dl = __ldg(&delta[(size_t)t * DINNER + d]);
        float ut = __ldg(&u[(size_t)t * DINNER + d]);
        float Bn = __ldg(&dbc[t * DBCN + DTRANK + n]);
        float Cn = __ldg(&dbc[t * DBCN + DTRANK + DSTATE + n]);

        float dA = __expf(dl * Adn);
        h = fmaf(dA, h, dl * ut * Bn);
        float v = h * Cn;
        v += __shfl_xor_sync(0xffffffffu, v, 8);
        v += __shfl_xor_sync(0xffffffffu, v, 4);
        v += __shfl_xor_sync(0xffffffffu, v, 2);
        v += __shfl_xor_sync(0xffffffffu, v, 1);
        if (n == 0) {
            float z = xz[(size_t)t * (2 * DINNER) + DINNER + d];
            float silu_z = z / (1.f + __expf(-z));
            y[(size_t)t * DINNER + d] = (v + ut * Dpd) * silu_z;
        }
    }
}

// ---------------------------------------------------------------------------
// kernel_launch
// ---------------------------------------------------------------------------
extern "C" void kernel_launch(void* const* d_in, const int* in_sizes, int n_in,
                              void* d_out, int out_size)
{
    const float* x = (const float*)d_in[0];
    const float* win[2]   = {(const float*)d_in[1],  (const float*)d_in[10]};
    const float* wconv[2] = {(const float*)d_in[2],  (const float*)d_in[11]};
    const float* bconv[2] = {(const float*)d_in[3],  (const float*)d_in[12]};
    const float* wx[2]    = {(const float*)d_in[4],  (const float*)d_in[13]};
    const float* wdt[2]   = {(const float*)d_in[5],  (const float*)d_in[14]};
    const float* bdt[2]   = {(const float*)d_in[6],  (const float*)d_in[15]};
    const float* Alog[2]  = {(const float*)d_in[7],  (const float*)d_in[16]};
    const float* Dp[2]    = {(const float*)d_in[8],  (const float*)d_in[17]};
    const float* wout[2]  = {(const float*)d_in[9],  (const float*)d_in[18]};
    const float* wproj    = (const float*)d_in[19];
    const float* bproj    = (const float*)d_in[20];

    float *xz, *u, *dbc, *delta, *y, *cat;
    cudaGetSymbolAddress((void**)&xz,    g_xz);
    cudaGetSymbolAddress((void**)&u,     g_u);
    cudaGetSymbolAddress((void**)&dbc,   g_dbc);
    cudaGetSymbolAddress((void**)&delta, g_delta);
    cudaGetSymbolAddress((void**)&y,     g_y);
    cudaGetSymbolAddress((void**)&cat,   g_cat);

    const size_t XZS = (size_t)SEQL * 2 * DINNER;
    const size_t US  = (size_t)SEQL * DINNER;
    const size_t DBS = (size_t)SEQL * DBCN;

    for (int dir = 0; dir < 2; dir++) {
        float* xzd  = xz    + dir * XZS;
        float* ud   = u     + dir * US;
        float* dbcd = dbc   + dir * DBS;
        float* deld = delta + dir * US;
        float* yd   = y     + dir * US;

        // 1) xz = x(dir-flipped) @ win^T   [2048 x 4096], K=1024
        gemm128<0><<<dim3(2 * DINNER / 128, SEQL / 128), 256>>>(
            x, win[dir], nullptr, xzd,
            SEQL, 2 * DINNER, DMODEL, DMODEL, DMODEL, 2 * DINNER,
            /*flipA=*/dir, 0, 0);

        // 2) depthwise conv + silu -> u
        conv_silu_kernel<<<(SEQL * DINNER) / 256, 256>>>(
            xzd, wconv[dir], bconv[dir], ud);

        // 3) dbc = u @ wx^T   [2048 x 96], K=2048  (skinny scalar tile)
        gemm_atb<32, 96, 16, 2, 6><<<dim3(1, SEQL / 32), 256>>>(
            ud, wx[dir], dbcd, SEQL, DBCN, DINNER, DINNER, DINNER, DBCN);

        // 4) delta = softplus(dt @ wdt^T + bdt)   [2048 x 2048], K=64
        gemm128<1><<<dim3(DINNER / 128, SEQL / 128), 256>>>(
            dbcd, wdt[dir], bdt[dir], deld,
            SEQL, DINNER, DTRANK, DBCN, DTRANK, DINNER, 0, 0, 0);

        // 5) selective scan -> y
        scan_kernel<<<(DINNER / 2) / 8, 256>>>(
            deld, ud, dbcd, xzd, Alog[dir], Dp[dir], yd);

        // 6) y @ wout^T -> cat[:, dir*1024:], rows un-flipped for b
        gemm128<0><<<dim3(DMODEL / 128, SEQL / 128), 256>>>(
            yd, wout[dir], nullptr, cat,
            SEQL, DMODEL, DINNER, DINNER, DINNER, 2 * DMODEL,
            0, /*flipC=*/dir, /*colOff=*/dir * DMODEL);
    }

    // 7) out = cat @ wproj^T + bproj   [2048 x 1024], K=2048
    gemm128<2><<<dim3(DMODEL / 128, SEQL / 128), 256>>>(
        cat, wproj, bproj, (float*)d_out,
        SEQL, DMODEL, 2 * DMODEL, 2 * DMODEL, 2 * DMODEL, DMODEL, 0, 0, 0);
}

// round 11
// speedup vs baseline: 1.8514x; 1.8206x over previous
#include <cuda_runtime.h>
#include <cuda_bf16.h>
#include <math.h>
#include <stdint.h>

// Problem constants
#define SEQL   2048
#define DMODEL 1024
#define DINNER 2048
#define DSTATE 16
#define DTRANK 64
#define DBCN   96

// ---------------------------------------------------------------------------
// Scratch (__device__ globals)
// ---------------------------------------------------------------------------
__device__ float g_xz[2][(size_t)SEQL * 2 * DINNER];
__device__ float g_u[2][(size_t)SEQL * DINNER];
__device__ float g_dbc[2][(size_t)SEQL * DBCN];
__device__ float g_delta[2][(size_t)SEQL * DINNER];
__device__ float g_y[2][(size_t)SEQL * DINNER];
__device__ float g_cat[(size_t)SEQL * 2 * DMODEL];

// ---------------------------------------------------------------------------
// mma.sync helpers (plain PTX, sm_80+, compiles for compute_103)
// ---------------------------------------------------------------------------
__device__ __forceinline__ uint32_t smem_u32(const void* p) {
    uint32_t a;
    asm("{ .reg .u64 t; cvta.to.shared.u64 t, %1; cvt.u32.u64 %0, t; }"
        : "=r"(a) : "l"(p));
    return a;
}
__device__ __forceinline__ void ldm_x4(uint32_t* r, uint32_t addr) {
    asm volatile("ldmatrix.sync.aligned.m8n8.x4.shared.b16 {%0,%1,%2,%3}, [%4];"
                 : "=r"(r[0]), "=r"(r[1]), "=r"(r[2]), "=r"(r[3]) : "r"(addr));
}
__device__ __forceinline__ void mma_bf16(float* c, const uint32_t* a, const uint32_t* b) {
    asm volatile(
        "mma.sync.aligned.m16n8k16.row.col.f32.bf16.bf16.f32 "
        "{%0,%1,%2,%3}, {%4,%5,%6,%7}, {%8,%9}, {%0,%1,%2,%3};"
        : "+f"(c[0]), "+f"(c[1]), "+f"(c[2]), "+f"(c[3])
        : "r"(a[0]), "r"(a[1]), "r"(a[2]), "r"(a[3]), "r"(b[0]), "r"(b[1]));
}

// split fp32x4 -> bf16 hi (4) + bf16 residual (4), packed as uint2 each
__device__ __forceinline__ void split4(float4 v, uint2& hi, uint2& lo) {
    __nv_bfloat162 h01 = __floats2bfloat162_rn(v.x, v.y);
    __nv_bfloat162 h23 = __floats2bfloat162_rn(v.z, v.w);
    __nv_bfloat162 l01 = __floats2bfloat162_rn(v.x - __bfloat162float(h01.x),
                                               v.y - __bfloat162float(h01.y));
    __nv_bfloat162 l23 = __floats2bfloat162_rn(v.z - __bfloat162float(h23.x),
                                               v.w - __bfloat162float(h23.y));
    hi.x = *(uint32_t*)&h01; hi.y = *(uint32_t*)&h23;
    lo.x = *(uint32_t*)&l01; lo.y = *(uint32_t*)&l23;
}

// ---------------------------------------------------------------------------
// Tensor-core (HMMA) 3-term bf16-split GEMM: C[M,N] = act(A[M,K] @ B[N,K]^T)
// Tile 128x128, BK=32, 512 threads (16 warps, 4x4 grid, 32x32 per warp).
// Requirements: M%128==0, N%128==0, K%32==0, rows 16B-aligned.
// ACT: 0 none, 1 bias+softplus, 2 bias.
// Dynamic smem: 2 buffers x 4 tiles (AH,AL,BH,BL) x 128 rows x 80 bytes.
// ---------------------------------------------------------------------------
#define ROWB  80                   // padded row stride (32 bf16 = 64B + 16B pad)
#define TILEB (128 * ROWB)         // 10240 bytes per tile
#define BUFB  (4 * TILEB)          // 40960 per buffer
#define GM_SMEM (2 * BUFB)         // 81920

template<int ACT>
__global__ void __launch_bounds__(512)
gemm_mma(const float* __restrict__ A, const float* __restrict__ B,
         const float* __restrict__ bias, float* __restrict__ C,
         int M, int N, int K, int lda, int ldb, int ldc,
         int flipA, int flipC, int colOffC)
{
    extern __shared__ char smem[];
    const uint32_t sb = smem_u32(smem);
    const int tid = threadIdx.x;
    const int wid = tid >> 5;
    const int lane = tid & 31;
    const int bm0 = blockIdx.y * 128;
    const int bn0 = blockIdx.x * 128;

    // warp tile: 32x32
    const int m_warp = (wid & 3) * 32;
    const int n_warp = (wid >> 2) * 32;

    // staging: each thread loads 2 float4 of A and 2 of B per BK=32 chunk
    const int q = tid & 7;          // k-quad (q*4)
    const int r = tid >> 3;         // rows r and r+64
    float4 stA[2], stB[2];

    float acc[2][4][4];
#pragma unroll
    for (int i = 0; i < 2; i++)
#pragma unroll
        for (int j = 0; j < 4; j++)
#pragma unroll
            for (int e = 0; e < 4; e++) acc[i][j][e] = 0.f;

    const int nIter = K / 32;

    auto LOAD = [&](int k0) {
        int g0 = bm0 + r, g1 = bm0 + r + 64;
        int a0 = flipA ? (M - 1 - g0) : g0;
        int a1 = flipA ? (M - 1 - g1) : g1;
        stA[0] = *reinterpret_cast<const float4*>(A + (size_t)a0 * lda + k0 + q * 4);
        stA[1] = *reinterpret_cast<const float4*>(A + (size_t)a1 * lda + k0 + q * 4);
        stB[0] = *reinterpret_cast<const float4*>(B + (size_t)(bn0 + r) * ldb + k0 + q * 4);
        stB[1] = *reinterpret_cast<const float4*>(B + (size_t)(bn0 + r + 64) * ldb + k0 + q * 4);
    };
    auto STORE = [&](int buf) {
        char* base = smem + buf * BUFB;
#pragma unroll
        for (int h = 0; h < 2; h++) {
            uint2 hi, lo;
            split4(stA[h], hi, lo);
            int row = r + h * 64;
            *(uint2*)(base + 0 * TILEB + row * ROWB + q * 8) = hi;
            *(uint2*)(base + 1 * TILEB + row * ROWB + q * 8) = lo;
            split4(stB[h], hi, lo);
            *(uint2*)(base + 2 * TILEB + row * ROWB + q * 8) = hi;
            *(uint2*)(base + 3 * TILEB + row * ROWB + q * 8) = lo;
        }
    };
    auto COMPUTE = [&](int buf) {
        const uint32_t bufb = sb + buf * BUFB;
#pragma unroll
        for (int ks = 0; ks < 2; ks++) {
            const int kb = ks * 16;
            uint32_t aF[2][2][4];   // [hi/lo][im][reg]
            uint32_t bF[2][4][2];   // [hi/lo][jn][reg]
            // A fragments: ldmatrix.x4 per (hl, im)
            {
                int rrow = (lane & 7) + ((lane >> 3) & 1) * 8;
                int kcol = kb + (lane >> 4) * 8;
#pragma unroll
                for (int hl = 0; hl < 2; hl++)
#pragma unroll
                    for (int im = 0; im < 2; im++) {
                        uint32_t addr = bufb + hl * TILEB +
                            (uint32_t)(m_warp + im * 16 + rrow) * ROWB + kcol * 2;
                        ldm_x4(aF[hl][im], addr);
                    }
            }
            // B fragments: each ldmatrix.x4 covers 2 n-tiles
            {
                int nrow = (lane & 7) + (lane >> 4) * 8;
                int kcol = kb + ((lane >> 3) & 1) * 8;
#pragma unroll
                for (int hl = 0; hl < 2; hl++)
#pragma unroll
                    for (int jp = 0; jp < 2; jp++) {
                        uint32_t rg[4];
                        uint32_t addr = bufb + (2 + hl) * TILEB +
                            (uint32_t)(n_warp + jp * 16 + nrow) * ROWB + kcol * 2;
                        ldm_x4(rg, addr);
                        bF[hl][jp * 2 + 0][0] = rg[0];
                        bF[hl][jp * 2 + 0][1] = rg[1];
                        bF[hl][jp * 2 + 1][0] = rg[2];
                        bF[hl][jp * 2 + 1][1] = rg[3];
                    }
            }
            // pass 0: AH*BH, pass 1: AH*BL, pass 2: AL*BH
#pragma unroll
            for (int im = 0; im < 2; im++)
#pragma unroll
                for (int jn = 0; jn < 4; jn++) mma_bf16(acc[im][jn], aF[0][im], bF[0][jn]);
#pragma unroll
            for (int im = 0; im < 2; im++)
#pragma unroll
                for (int jn = 0; jn < 4; jn++) mma_bf16(acc[im][jn], aF[0][im], bF[1][jn]);
#pragma unroll
            for (int im = 0; im < 2; im++)
#pragma unroll
                for (int jn = 0; jn < 4; jn++) mma_bf16(acc[im][jn], aF[1][im], bF[0][jn]);
        }
    };

    LOAD(0);
    STORE(0);
    __syncthreads();

    int buf = 0;
    for (int it = 0; it < nIter; it++) {
        if (it + 1 < nIter) LOAD((it + 1) * 32);     // LDGs overlap compute
        COMPUTE(buf);
        if (it + 1 < nIter) {
            STORE(buf ^ 1);                          // other buffer: no hazard
            __syncthreads();
        }
        buf ^= 1;
    }

    // epilogue: c0,c1 = row g, cols 2c..2c+1 ; c2,c3 = row g+8
    const int g = lane >> 2;
    const int cc = (lane & 3) * 2;
#pragma unroll
    for (int im = 0; im < 2; im++) {
#pragma unroll
        for (int jn = 0; jn < 4; jn++) {
            int col = bn0 + n_warp + jn * 8 + cc;
            float v0 = acc[im][jn][0], v1 = acc[im][jn][1];
            float v2 = acc[im][jn][2], v3 = acc[im][jn][3];
            if (ACT != 0) {
                float b0 = bias[col], b1 = bias[col + 1];
                v0 += b0; v1 += b1; v2 += b0; v3 += b1;
                if (ACT == 1) {
                    v0 = (v0 > 20.f) ? v0 : log1pf(expf(v0));
                    v1 = (v1 > 20.f) ? v1 : log1pf(expf(v1));
                    v2 = (v2 > 20.f) ? v2 : log1pf(expf(v2));
                    v3 = (v3 > 20.f) ? v3 : log1pf(expf(v3));
                }
            }
            int r0 = bm0 + m_warp + im * 16 + g;
            int r1 = r0 + 8;
            int o0 = flipC ? (M - 1 - r0) : r0;
            int o1 = flipC ? (M - 1 - r1) : r1;
            *reinterpret_cast<float2*>(C + (size_t)o0 * ldc + colOffC + col) =
                make_float2(v0, v1);
            *reinterpret_cast<float2*>(C + (size_t)o1 * ldc + colOffC + col) =
                make_float2(v2, v3);
        }
    }
}

// ---------------------------------------------------------------------------
// Skinny scalar SGEMM (N=96), both directions via blockIdx.z.
// ---------------------------------------------------------------------------
__global__ void __launch_bounds__(256)
gemm_skinny(const float* __restrict__ u0, const float* __restrict__ u1,
            const float* __restrict__ w0, const float* __restrict__ w1,
            float* __restrict__ c0, float* __restrict__ c1)
{
    constexpr int BM = 32, BN = 96, BK = 16, TM = 2, TN = 6;
    const float* A = blockIdx.z ? u1 : u0;
    const float* B = blockIdx.z ? w1 : w0;
    float* C = blockIdx.z ? c1 : c0;
    const int N = DBCN, K = DINNER;

    __shared__ float As[BK][BM + 4];
    __shared__ float Bs[BK][BN + 4];
    const int tid = threadIdx.x;
    const int bm0 = blockIdx.y * BM;
    const int tr = tid / 16, tc = tid % 16;

    float acc[TM][TN];
#pragma unroll
    for (int i = 0; i < TM; i++)
#pragma unroll
        for (int j = 0; j < TN; j++) acc[i][j] = 0.f;

    for (int k0 = 0; k0 < K; k0 += BK) {
        for (int e = tid; e < BM * (BK / 4); e += 256) {
            int rr = e / 4, k4 = e % 4;
            const float4 v = *reinterpret_cast<const float4*>(
                A + (size_t)(bm0 + rr) * K + k0 + k4 * 4);
            As[k4 * 4 + 0][rr] = v.x; As[k4 * 4 + 1][rr] = v.y;
            As[k4 * 4 + 2][rr] = v.z; As[k4 * 4 + 3][rr] = v.w;
        }
        for (int e = tid; e < BN * (BK / 4); e += 256) {
            int c = e / 4, k4 = e % 4;
            const float4 v = *reinterpret_cast<const float4*>(
                B + (size_t)c * K + k0 + k4 * 4);
            Bs[k4 * 4 + 0][c] = v.x; Bs[k4 * 4 + 1][c] = v.y;
            Bs[k4 * 4 + 2][c] = v.z; Bs[k4 * 4 + 3][c] = v.w;
        }
        __syncthreads();
#pragma unroll
        for (int kk = 0; kk < BK; kk++) {
            float ra[TM], rb[TN];
#pragma unroll
            for (int i = 0; i < TM; i++) ra[i] = As[kk][tr * TM + i];
#pragma unroll
            for (int j = 0; j < TN; j++) rb[j] = Bs[kk][tc * TN + j];
#pragma unroll
            for (int i = 0; i < TM; i++)
#pragma unroll
                for (int j = 0; j < TN; j++)
                    acc[i][j] = fmaf(ra[i], rb[j], acc[i][j]);
        }
        __syncthreads();
    }
#pragma unroll
    for (int i = 0; i < TM; i++)
#pragma unroll
        for (int j = 0; j < TN; j++) {
            int gc = tc * TN + j;
            if (gc < N) C[(size_t)(bm0 + tr * TM + i) * N + gc] = acc[i][j];
        }
}

// ---------------------------------------------------------------------------
// Depthwise causal conv + bias + silu (both dirs: blockIdx.y)
// ---------------------------------------------------------------------------
__global__ void conv_silu_kernel(const float* __restrict__ xz,
                                 const float* __restrict__ wconv0,
                                 const float* __restrict__ wconv1,
                                 const float* __restrict__ bconv0,
                                 const float* __restrict__ bconv1,
                                 float* __restrict__ u)
{
    const int dirv = blockIdx.y;
    const float* wconv = dirv ? wconv1 : wconv0;
    const float* bconv = dirv ? bconv1 : bconv0;
    const float* xzd = xz + (size_t)dirv * SEQL * 2 * DINNER;
    float* ud = u + (size_t)dirv * SEQL * DINNER;

    int idx = blockIdx.x * blockDim.x + threadIdx.x;
    int t = idx >> 11;
    int d = idx & (DINNER - 1);
    const float* col = xzd + d;
    float w0 = wconv[d * 4 + 0], w1 = wconv[d * 4 + 1];
    float w2 = wconv[d * 4 + 2], w3 = wconv[d * 4 + 3];
    float s = bconv[d];
    if (t >= 3) s = fmaf(col[(size_t)(t - 3) * (2 * DINNER)], w0, s);
    if (t >= 2) s = fmaf(col[(size_t)(t - 2) * (2 * DINNER)], w1, s);
    if (t >= 1) s = fmaf(col[(size_t)(t - 1) * (2 * DINNER)], w2, s);
    s = fmaf(col[(size_t)t * (2 * DINNER)], w3, s);
    ud[idx] = s / (1.f + __expf(-s));
}

// ---------------------------------------------------------------------------
// Selective scan, both dirs in one launch (blockIdx.y = dir).
// ---------------------------------------------------------------------------
__global__ void scan_kernel(const float* __restrict__ delta,
                            const float* __restrict__ u,
                            const float* __restrict__ dbc,
                            const float* __restrict__ xz,
                            const float* __restrict__ Alog0,
                            const float* __restrict__ Alog1,
                            const float* __restrict__ Dp0,
                            const float* __restrict__ Dp1,
                            float* __restrict__ y)
{
    const int dirv = blockIdx.y;
    const float* deld = delta + (size_t)dirv * SEQL * DINNER;
    const float* ud   = u     + (size_t)dirv * SEQL * DINNER;
    const float* dbcd = dbc   + (size_t)dirv * SEQL * DBCN;
    const float* xzd  = xz    + (size_t)dirv * SEQL * 2 * DINNER;
    const float* Alog = dirv ? Alog1 : Alog0;
    const float* Dp   = dirv ? Dp1 : Dp0;
    float* yd = y + (size_t)dirv * SEQL * DINNER;

    int warp = (blockIdx.x * blockDim.x + threadIdx.x) >> 5;
    int lane = threadIdx.x & 31;
    int n = lane & 15;
    int d = warp * 2 + (lane >> 4);

    float Adn = -expf(Alog[d * DSTATE + n]);
    float Dpd = Dp[d];
    float h = 0.f;

    for (int t = 0; t < SEQL; t++) {
        float dl = __ldg(&deld[(size_t)t * DINNER + d]);
        float ut = __ldg(&ud[(size_t)t * DINNER + d]);
        float Bn = __ldg(&dbcd[t * DBCN + DTRANK + n]);
        float Cn = __ldg(&dbcd[t * DBCN + DTRANK + DSTATE + n]);

        float dA = __expf(dl * Adn);
        h = fmaf(dA, h, dl * ut * Bn);
        float v = h * Cn;
        v += __shfl_xor_sync(0xffffffffu, v, 8);
        v += __shfl_xor_sync(0xffffffffu, v, 4);
        v += __shfl_xor_sync(0xffffffffu, v, 2);
        v += __shfl_xor_sync(0xffffffffu, v, 1);
        if (n == 0) {
            float z = xzd[(size_t)t * (2 * DINNER) + DINNER + d];
            float silu_z = z / (1.f + __expf(-z));
            yd[(size_t)t * DINNER + d] = (v + ut * Dpd) * silu_z;
        }
    }
}

// ---------------------------------------------------------------------------
// kernel_launch
// ---------------------------------------------------------------------------
extern "C" void kernel_launch(void* const* d_in, const int* in_sizes, int n_in,
                              void* d_out, int out_size)
{
    const float* x = (const float*)d_in[0];
    const float* win[2]   = {(const float*)d_in[1],  (const float*)d_in[10]};
    const float* wconv[2] = {(const float*)d_in[2],  (const float*)d_in[11]};
    const float* bconv[2] = {(const float*)d_in[3],  (const float*)d_in[12]};
    const float* wx[2]    = {(const float*)d_in[4],  (const float*)d_in[13]};
    const float* wdt[2]   = {(const float*)d_in[5],  (const float*)d_in[14]};
    const float* bdt[2]   = {(const float*)d_in[6],  (const float*)d_in[15]};
    const float* Alog[2]  = {(const float*)d_in[7],  (const float*)d_in[16]};
    const float* Dp[2]    = {(const float*)d_in[8],  (const float*)d_in[17]};
    const float* wout[2]  = {(const float*)d_in[9],  (const float*)d_in[18]};
    const float* wproj    = (const float*)d_in[19];
    const float* bproj    = (const float*)d_in[20];

    cudaFuncSetAttribute(gemm_mma<0>, cudaFuncAttributeMaxDynamicSharedMemorySize, GM_SMEM);
    cudaFuncSetAttribute(gemm_mma<1>, cudaFuncAttributeMaxDynamicSharedMemorySize, GM_SMEM);
    cudaFuncSetAttribute(gemm_mma<2>, cudaFuncAttributeMaxDynamicSharedMemorySize, GM_SMEM);

    float *xz, *u, *dbc, *delta, *y, *cat;
    cudaGetSymbolAddress((void**)&xz,    g_xz);
    cudaGetSymbolAddress((void**)&u,     g_u);
    cudaGetSymbolAddress((void**)&dbc,   g_dbc);
    cudaGetSymbolAddress((void**)&delta, g_delta);
    cudaGetSymbolAddress((void**)&y,     g_y);
    cudaGetSymbolAddress((void**)&cat,   g_cat);

    const size_t XZS = (size_t)SEQL * 2 * DINNER;
    const size_t US  = (size_t)SEQL * DINNER;
    const size_t DBS = (size_t)SEQL * DBCN;

    // 1) xz = x(flip per dir) @ win^T   [2048 x 4096], K=1024
    for (int dir = 0; dir < 2; dir++)
        gemm_mma<0><<<dim3(4096 / 128, SEQL / 128), 512, GM_SMEM>>>(
            x, win[dir], nullptr, xz + dir * XZS,
            SEQL, 2 * DINNER, DMODEL, DMODEL, DMODEL, 2 * DINNER,
            /*flipA=*/dir, 0, 0);

    // 2) conv + silu (both dirs)
    conv_silu_kernel<<<dim3((SEQL * DINNER) / 256, 2), 256>>>(
        xz, wconv[0], wconv[1], bconv[0], bconv[1], u);

    // 3) dbc = u @ wx^T  [2048 x 96], K=2048 (both dirs)
    gemm_skinny<<<dim3(1, SEQL / 32, 2), 256>>>(
        u, u + US, wx[0], wx[1], dbc, dbc + DBS);

    // 4) delta = softplus(dt @ wdt^T + bdt)  [2048 x 2048], K=64 (lda=96)
    for (int dir = 0; dir < 2; dir++)
        gemm_mma<1><<<dim3(DINNER / 128, SEQL / 128), 512, GM_SMEM>>>(
            dbc + dir * DBS, wdt[dir], bdt[dir], delta + dir * US,
            SEQL, DINNER, DTRANK, DBCN, DTRANK, DINNER, 0, 0, 0);

    // 5) selective scan (both dirs)
    scan_kernel<<<dim3((DINNER / 2) / 8, 2), 256>>>(
        delta, u, dbc, xz, Alog[0], Alog[1], Dp[0], Dp[1], y);

    // 6) y @ wout^T -> cat[:, dir*1024:], rows un-flipped for dir b
    for (int dir = 0; dir < 2; dir++)
        gemm_mma<0><<<dim3(DMODEL / 128, SEQL / 128), 512, GM_SMEM>>>(
            y + dir * US, wout[dir], nullptr, cat,
            SEQL, DMODEL, DINNER, DINNER, DINNER, 2 * DMODEL,
            0, /*flipC=*/dir, /*colOff=*/dir * DMODEL);

    // 7) out = cat @ wproj^T + bproj  [2048 x 1024], K=2048
    gemm_mma<2><<<dim3(DMODEL / 128, SEQL / 128), 512, GM_SMEM>>>(
        cat, wproj, bproj, (float*)d_out,
        SEQL, DMODEL, 2 * DMODEL, 2 * DMODEL, 2 * DMODEL, DMODEL, 0, 0, 0);
}